// round 2
// baseline (speedup 1.0000x reference)
#include <cuda_runtime.h>
#include <math.h>

// Problem constants (fixed shapes from setup_inputs)
#define Bb 4
#define Gg 128
#define Nn 2048
#define Pp 4
#define Ff 64
#define BP 16           // B*P
#define ZTOL 1e-9f
#define NCHUNKS 128     // 16 rows per chunk
#define CHROWS 16
#define NTILES 16       // 128 rows per K4 tile
#define MAXNNZ (1 << 19)

// ---------------- scratch (device globals) ----------------
__device__ __align__(16) float  g_Wx[BP * Nn * Ff];     // [bp][n][f] 8MB
__device__ __align__(16) float4 g_T1n[Nn * BP];         // [n][bp]: (s1, e^s1, e^{0.2 s1}, 0)
__device__ __align__(16) float4 g_T2n[Nn * BP];         // [m][bp]: (s2, e^{s2}/D, e^{0.2 s2}/D, 0)
__device__ float  g_s2n[Nn * BP];                       // [n][bp]
__device__ int    g_cnt2[NCHUNKS * Nn];
__device__ int    g_off2[NCHUNKS * Nn];
__device__ int    g_colptr[Nn + 1];
__device__ int    g_tp[Nn * (NTILES + 1)];              // per (col, tile) entry ranges
__device__ int    g_rowidx[MAXNNZ];
__device__ int    g_colidx[MAXNNZ];
__device__ float  g_vals[MAXNNZ];
__device__ __align__(16) float2 g_mw[BP * MAXNNZ];      // [bp][i]: (tileoff_bits, weight)

// ---------------------------------------------------------------------------
// K1: Wx[bp][n][f] = sum_g W[p][f][g] * x[b][g][n]; plus s1/s2 exp tables.
// ---------------------------------------------------------------------------
__global__ void k1_wx(const float* __restrict__ x, const float* __restrict__ a,
                      const float* __restrict__ W) {
    const int b = blockIdx.z, p = blockIdx.y;
    const int n = blockIdx.x * 256 + threadIdx.x;

    __shared__ __align__(16) float Ws[Gg * Ff];  // [g][f]
    __shared__ float as[2 * Ff];

    for (int i = threadIdx.x; i < Gg * Ff; i += 256) {
        int f = i >> 7, g = i & 127;
        Ws[g * Ff + f] = W[(p * Ff + f) * Gg + g];
    }
    if (threadIdx.x < 2 * Ff) as[threadIdx.x] = a[p * 2 * Ff + threadIdx.x];
    __syncthreads();

    float4 acc[16];
#pragma unroll
    for (int i = 0; i < 16; i++) acc[i] = make_float4(0.f, 0.f, 0.f, 0.f);

    const float* xb = x + ((size_t)b * Gg) * Nn + n;
    const float4* Ws4 = (const float4*)Ws;

    for (int g = 0; g < Gg; g++) {
        float xv = xb[(size_t)g * Nn];
#pragma unroll
        for (int i = 0; i < 16; i++) {
            float4 w = Ws4[g * 16 + i];
            acc[i].x += w.x * xv; acc[i].y += w.y * xv;
            acc[i].z += w.z * xv; acc[i].w += w.w * xv;
        }
    }

    const int bp = b * Pp + p;
    float4* dst = (float4*)(g_Wx + ((size_t)(bp * Nn + n)) * Ff);
    float s1 = 0.f, s2 = 0.f;
#pragma unroll
    for (int i = 0; i < 16; i++) {
        dst[i] = acc[i];
        s1 += as[4*i+0] * acc[i].x + as[4*i+1] * acc[i].y
            + as[4*i+2] * acc[i].z + as[4*i+3] * acc[i].w;
        s2 += as[Ff+4*i+0] * acc[i].x + as[Ff+4*i+1] * acc[i].y
            + as[Ff+4*i+2] * acc[i].z + as[Ff+4*i+3] * acc[i].w;
    }
    g_T1n[n * BP + bp] = make_float4(s1, __expf(s1), __expf(0.2f * s1), 0.f);
    g_s2n[n * BP + bp] = s2;
}

// ---------------------------------------------------------------------------
// K2: warp per row m; ballot-compressed masked scan; lanes 0-15 = bp.
// D[bp][m] = sum_{masked n} exp(leaky(s2+s1)) via exp-product tables (no MUFU
// in the hot loop). Writes T2n[m][bp] = (s2, e^{s2}/D, e^{0.2 s2}/D, 0).
// ---------------------------------------------------------------------------
__global__ void k2_rowstats(const float* __restrict__ S) {
    const int w = threadIdx.x >> 5, lane = threadIdx.x & 31;
    const int m = blockIdx.x * 8 + w;

    float s2l = 0.f, e2a = 0.f, e2b = 0.f;
    if (lane < BP) {
        s2l = g_s2n[m * BP + lane];
        e2a = __expf(s2l);
        e2b = __expf(0.2f * s2l);
    }
    float D = 0.f;
    const float* row = S + (size_t)m * Nn;

    for (int c = 0; c < Nn / 32; c++) {
        int n = c * 32 + lane;
        float sv = row[n];
        float adj = sv + (n == m ? 1.f : 0.f);
        unsigned bmask = __ballot_sync(0xffffffffu, fabsf(adj) > ZTOL);
        while (bmask) {
            int j = __ffs(bmask) - 1;
            bmask &= bmask - 1;
            int ne = c * 32 + j;
            if (lane < BP) {
                float4 t1 = g_T1n[ne * BP + lane];
                float t = s2l + t1.x;
                D += (t >= 0.f) ? e2a * t1.y : e2b * t1.z;
            }
        }
    }
    if (lane < BP) {
        float ci = (D > 0.f) ? 1.f / D : 0.f;
        g_T2n[m * BP + lane] = make_float4(s2l, e2a * ci, e2b * ci, 0.f);
    }
}

// ---------------------------------------------------------------------------
// K3: deterministic CSC of S. 16-row chunks for parallelism.
// ---------------------------------------------------------------------------
__global__ void k3_count(const float* __restrict__ S) {
    const int n = blockIdx.x * 256 + threadIdx.x;
    const int mc = blockIdx.y;
    int c = 0;
    const int m0 = mc * CHROWS;
#pragma unroll
    for (int mm = 0; mm < CHROWS; mm++) {
        float sv = S[(size_t)(m0 + mm) * Nn + n];
        if (fabsf(sv) > ZTOL) c++;
    }
    g_cnt2[mc * Nn + n] = c;
}

__global__ void k3_scan() {  // single block, 1024 threads: scan 2048 col totals
    __shared__ int s[Nn];
    const int tid = threadIdx.x;
    const int n0 = tid, n1 = tid + 1024;
    int tot0 = 0, tot1 = 0;
    for (int mc = 0; mc < NCHUNKS; mc++) {
        tot0 += g_cnt2[mc * Nn + n0];
        tot1 += g_cnt2[mc * Nn + n1];
    }
    s[n0] = tot0; s[n1] = tot1;
    __syncthreads();
    for (int off = 1; off < Nn; off <<= 1) {
        int a0 = (n0 >= off) ? s[n0 - off] : 0;
        int a1 = (n1 >= off) ? s[n1 - off] : 0;
        __syncthreads();
        s[n0] += a0; s[n1] += a1;
        __syncthreads();
    }
    g_colptr[n0] = s[n0] - tot0;
    g_colptr[n1] = s[n1] - tot1;
    if (tid == 1023) g_colptr[Nn] = s[Nn - 1];
}

// Per-chunk exclusive offsets + per-(col, 128-row-tile) entry ranges.
__global__ void k3_scan2() {
    const int n = blockIdx.x * 256 + threadIdx.x;
    int run = g_colptr[n];
    for (int mc = 0; mc < NCHUNKS; mc++) {
        if ((mc & 7) == 0) g_tp[n * (NTILES + 1) + (mc >> 3)] = run;
        g_off2[mc * Nn + n] = run;
        run += g_cnt2[mc * Nn + n];
    }
    g_tp[n * (NTILES + 1) + NTILES] = run;
}

__global__ void k3_fill(const float* __restrict__ S) {
    const int n = blockIdx.x * 256 + threadIdx.x;
    const int mc = blockIdx.y;
    int off = g_off2[mc * Nn + n];
    const int m0 = mc * CHROWS;
#pragma unroll
    for (int mm = 0; mm < CHROWS; mm++) {
        int m = m0 + mm;
        float sv = S[(size_t)m * Nn + n];
        if (fabsf(sv) > ZTOL && off < MAXNNZ) {
            g_rowidx[off] = m;
            g_colidx[off] = n;
            g_vals[off] = sv;
            off++;
        }
    }
}

// ---------------------------------------------------------------------------
// KW: weights per (bp, entry): wgt = S * exp(leaky(s2+s1)) / D via tables.
// Stream layout g_mw[bp][i] = (tile-local float-offset bits, wgt).
// ---------------------------------------------------------------------------
__global__ void k_weights() {
    const int total = g_colptr[Nn];
    const int stride = gridDim.x * blockDim.x;
    for (int i = blockIdx.x * blockDim.x + threadIdx.x; i < total; i += stride) {
        int m = g_rowidx[i], n = g_colidx[i];
        float sval = g_vals[i];
        int mo = (m & 127) * Ff;   // float offset within 128-row tile
#pragma unroll
        for (int bp = 0; bp < BP; bp++) {
            float4 t1 = g_T1n[n * BP + bp];
            float4 t2 = g_T2n[m * BP + bp];
            float t = t1.x + t2.x;
            float wgt = sval * ((t >= 0.f) ? t2.y * t1.y : t2.z * t1.z);
            g_mw[bp * MAXNNZ + i] = make_float2(__int_as_float(mo), wgt);
        }
    }
}

// ---------------------------------------------------------------------------
// K4: block = (bp, 256-column tile). 8 warps x 32 cols, lanes = f-pairs.
// Wx staged in 32KB smem per 128-row tile; entries consumed from g_mw streams.
// ---------------------------------------------------------------------------
#define CCOLS 256
#define EPIPAD 261   // padded f-major epilogue stride (261 % 32 = 5, odd)

__global__ void __launch_bounds__(256, 1) k4_out(float* __restrict__ out) {
    __shared__ __align__(16) float smem[32 * EPIPAD >= 128 * Ff ? 32 * EPIPAD : 128 * Ff];
    const int bp = blockIdx.y;
    const int n0 = blockIdx.x * CCOLS;
    const int w = threadIdx.x >> 5, lane = threadIdx.x & 31;
    const int nw0 = n0 + w * 32;

    float acc0[32], acc1[32];
#pragma unroll
    for (int k = 0; k < 32; k++) { acc0[k] = 0.f; acc1[k] = 0.f; }

    const float4* wxsrc = (const float4*)(g_Wx + (size_t)bp * Nn * Ff);
    const float2* __restrict__ mw = g_mw + (size_t)bp * MAXNNZ;

    for (int t = 0; t < NTILES; t++) {
        const float4* src = wxsrc + t * 128 * (Ff / 4);
        float4* dst4 = (float4*)smem;
#pragma unroll
        for (int q = 0; q < 8; q++)
            dst4[threadIdx.x + q * 256] = src[threadIdx.x + q * 256];
        __syncthreads();

#pragma unroll
        for (int k = 0; k < 32; k++) {
            const int n = nw0 + k;
            int lo = g_tp[n * (NTILES + 1) + t];
            int hi = g_tp[n * (NTILES + 1) + t + 1];
            float a0 = acc0[k], a1 = acc1[k];
            for (int i = lo; i < hi; i++) {
                float2 e = mw[i];
                int mo = __float_as_int(e.x);
                float2 wx = *(const float2*)(smem + mo + 2 * lane);
                a0 = fmaf(e.y, wx.x, a0);
                a1 = fmaf(e.y, wx.y, a1);
            }
            acc0[k] = a0; acc1[k] = a1;
        }
        __syncthreads();
    }

    // Epilogue: per-warp transpose through padded smem, coalesced stores.
    // Warp w owns cols [nw0, nw0+32); layout smem[f_local*EPIPAD + col_local].
    const int b = bp >> 2, p = bp & 3;
#pragma unroll
    for (int h = 0; h < 2; h++) {        // f halves [0,32) and [32,64)
        if ((lane >> 4) == h) {
            int fl = (lane & 15) * 2;    // f-local within half
#pragma unroll
            for (int k = 0; k < 32; k++) {
                smem[fl * EPIPAD + w * 32 + k]       = fmaxf(acc0[k], 0.f);
                smem[(fl + 1) * EPIPAD + w * 32 + k] = fmaxf(acc1[k], 0.f);
            }
        }
        __syncwarp();
        const int nn = nw0 + lane;
        size_t obase = ((size_t)b * (Pp * Ff) + p * Ff + h * 32) * Nn + nn;
#pragma unroll
        for (int ff = 0; ff < 32; ff++)
            out[obase + (size_t)ff * Nn] = smem[ff * EPIPAD + w * 32 + lane];
        __syncwarp();
    }
}

// ---------------------------------------------------------------------------
extern "C" void kernel_launch(void* const* d_in, const int* in_sizes, int n_in,
                              void* d_out, int out_size) {
    const float* x = (const float*)d_in[0];  // (4,128,2048)
    const float* a = (const float*)d_in[1];  // (4,1,128)
    const float* W = (const float*)d_in[2];  // (4,1,64,128)
    const float* S = (const float*)d_in[3];  // (1,2048,2048)
    float* out = (float*)d_out;              // (4,256,2048)

    k1_wx<<<dim3(8, Pp, Bb), 256>>>(x, a, W);
    k3_count<<<dim3(8, NCHUNKS), 256>>>(S);
    k3_scan<<<1, 1024>>>();
    k3_scan2<<<8, 256>>>();
    k3_fill<<<dim3(8, NCHUNKS), 256>>>(S);
    k2_rowstats<<<Nn / 8, 256>>>(S);
    k_weights<<<1024, 256>>>();
    k4_out<<<dim3(Nn / CCOLS, BP), 256>>>(out);
}

// round 4
// speedup vs baseline: 1.3100x; 1.3100x over previous
#include <cuda_runtime.h>
#include <math.h>

#define Bb 4
#define Gg 128
#define Nn 2048
#define Pp 4
#define Ff 64
#define BP 16
#define ZTOL 1e-9f
#define NCH 32          // 32 chunks of 64 rows
#define CHR 64
#define NTILES 16       // 128-row tiles in k4
#define MAXNNZ (1 << 19)
#define K4COLS 128      // columns per k4 block

// ---------------- scratch ----------------
__device__ __align__(16) float  g_Wx[BP * Nn * Ff];   // [bp][n][f] 8MB
__device__ __align__(16) float4 g_T1n[Nn * BP];       // [n][bp]: (s1, e^s1, e^{.2 s1}, 0)
__device__ __align__(16) float4 g_T2n[Nn * BP];       // [m][bp]: (s2, e^{s2}/D, e^{.2 s2}/D, 0)
__device__ float g_s2n[Nn * BP];                      // [n][bp]
__device__ int   g_cnt[Nn * NCH];                     // [n][mc]
__device__ int   g_off2[Nn * NCH];                    // [n][mc] local exclusive
__device__ int   g_tot[Nn];
__device__ int   g_colptr[Nn + 1];
__device__ int   g_tp[(NTILES + 1) * Nn];             // [t][n]
__device__ int   g_rowidx[MAXNNZ];
__device__ int   g_colidx[MAXNNZ];
__device__ float g_vals[MAXNNZ];
__device__ __align__(16) float2 g_mw[BP * MAXNNZ];    // [bp][i]: (tile-off bits, wgt)

// ---------------------------------------------------------------------------
// K1: Wx = W @ x per (b,p); also s1/s2 and exp tables.
// ---------------------------------------------------------------------------
__global__ void k1_wx(const float* __restrict__ x, const float* __restrict__ a,
                      const float* __restrict__ W) {
    const int b = blockIdx.z, p = blockIdx.y;
    const int n = blockIdx.x * 256 + threadIdx.x;

    __shared__ __align__(16) float Ws[Gg * Ff];
    __shared__ float as[2 * Ff];

    for (int i = threadIdx.x; i < Gg * Ff; i += 256) {
        int f = i >> 7, g = i & 127;
        Ws[g * Ff + f] = W[(p * Ff + f) * Gg + g];
    }
    if (threadIdx.x < 2 * Ff) as[threadIdx.x] = a[p * 2 * Ff + threadIdx.x];
    __syncthreads();

    float4 acc[16];
#pragma unroll
    for (int i = 0; i < 16; i++) acc[i] = make_float4(0.f, 0.f, 0.f, 0.f);

    const float* xb = x + ((size_t)b * Gg) * Nn + n;
    const float4* Ws4 = (const float4*)Ws;

    for (int g = 0; g < Gg; g++) {
        float xv = xb[(size_t)g * Nn];
#pragma unroll
        for (int i = 0; i < 16; i++) {
            float4 w = Ws4[g * 16 + i];
            acc[i].x += w.x * xv; acc[i].y += w.y * xv;
            acc[i].z += w.z * xv; acc[i].w += w.w * xv;
        }
    }

    const int bp = b * Pp + p;
    float4* dst = (float4*)(g_Wx + ((size_t)(bp * Nn + n)) * Ff);
    float s1 = 0.f, s2 = 0.f;
#pragma unroll
    for (int i = 0; i < 16; i++) {
        dst[i] = acc[i];
        s1 += as[4*i+0]*acc[i].x + as[4*i+1]*acc[i].y + as[4*i+2]*acc[i].z + as[4*i+3]*acc[i].w;
        s2 += as[Ff+4*i+0]*acc[i].x + as[Ff+4*i+1]*acc[i].y + as[Ff+4*i+2]*acc[i].z + as[Ff+4*i+3]*acc[i].w;
    }
    g_T1n[n * BP + bp] = make_float4(s1, __expf(s1), __expf(0.2f * s1), 0.f);
    g_s2n[n * BP + bp] = s2;
}

// ---------------------------------------------------------------------------
// K2: softmax normalizer per (m,bp) via exp-product tables (no MUFU in loop).
// Block per row m; threads strided over n.
// ---------------------------------------------------------------------------
__global__ void k2_rowstats(const float* __restrict__ S) {
    const int m = blockIdx.x;
    const int tid = threadIdx.x;

    __shared__ float s2s[BP], eas[BP], ebs[BP];
    __shared__ float red[8][BP];
    if (tid < BP) {
        float s2 = g_s2n[m * BP + tid];
        s2s[tid] = s2; eas[tid] = __expf(s2); ebs[tid] = __expf(0.2f * s2);
    }
    __syncthreads();

    float D[BP];
#pragma unroll
    for (int bp = 0; bp < BP; bp++) D[bp] = 0.f;

    const float* row = S + (size_t)m * Nn;
    for (int n = tid; n < Nn; n += 256) {
        float adj = row[n] + (n == m ? 1.f : 0.f);
        if (fabsf(adj) > ZTOL) {
            const float4* t1p = &g_T1n[n * BP];
#pragma unroll
            for (int bp = 0; bp < BP; bp++) {
                float4 t1 = t1p[bp];
                float t = s2s[bp] + t1.x;
                D[bp] += (t >= 0.f) ? eas[bp] * t1.y : ebs[bp] * t1.z;
            }
        }
    }

#pragma unroll
    for (int bp = 0; bp < BP; bp++) {
#pragma unroll
        for (int off = 16; off; off >>= 1)
            D[bp] += __shfl_down_sync(0xffffffffu, D[bp], off);
    }
    const int w = tid >> 5, l = tid & 31;
    if (l == 0) {
#pragma unroll
        for (int bp = 0; bp < BP; bp++) red[w][bp] = D[bp];
    }
    __syncthreads();
    if (tid < BP) {
        float d = 0.f;
#pragma unroll
        for (int ww = 0; ww < 8; ww++) d += red[ww][tid];
        float ci = (d > 0.f) ? 1.f / d : 0.f;
        g_T2n[m * BP + tid] = make_float4(s2s[tid], eas[tid] * ci, ebs[tid] * ci, 0.f);
    }
}

// ---------------------------------------------------------------------------
// K3: deterministic CSC build.
// ---------------------------------------------------------------------------
__global__ void k3_count(const float* __restrict__ S) {
    const int n = blockIdx.x * 256 + threadIdx.x;
    const int mc = blockIdx.y;
    int c = 0;
    const int m0 = mc * CHR;
#pragma unroll 8
    for (int mm = 0; mm < CHR; mm++)
        if (fabsf(S[(size_t)(m0 + mm) * Nn + n]) > ZTOL) c++;
    g_cnt[n * NCH + mc] = c;
}

// warp per column: shuffle-scan the 32 chunk counts
__global__ void k3_offs() {
    const int n = blockIdx.x * 8 + (threadIdx.x >> 5);
    const int lane = threadIdx.x & 31;
    int c = g_cnt[n * NCH + lane];
    int v = c;
#pragma unroll
    for (int off = 1; off < 32; off <<= 1) {
        int u = __shfl_up_sync(0xffffffffu, v, off);
        if (lane >= off) v += u;
    }
    g_off2[n * NCH + lane] = v - c;
    if (lane == 31) g_tot[n] = v;
}

__global__ void k3_scan() {  // one block, 1024 threads: colptr over 2048 totals
    __shared__ int s[Nn];
    const int tid = threadIdx.x;
    const int n0 = tid, n1 = tid + 1024;
    int t0 = g_tot[n0], t1 = g_tot[n1];
    s[n0] = t0; s[n1] = t1;
    __syncthreads();
    for (int off = 1; off < Nn; off <<= 1) {
        int a0 = (n0 >= off) ? s[n0 - off] : 0;
        int a1 = (n1 >= off) ? s[n1 - off] : 0;
        __syncthreads();
        s[n0] += a0; s[n1] += a1;
        __syncthreads();
    }
    g_colptr[n0] = s[n0] - t0;
    g_colptr[n1] = s[n1] - t1;
    if (tid == 1023) g_colptr[Nn] = s[Nn - 1];
}

__global__ void k3_tp() {    // tp[t][n] for t=0..16
    int idx = blockIdx.x * 256 + threadIdx.x;   // 2048*17
    if (idx >= (NTILES + 1) * Nn) return;
    int t = idx / Nn, n = idx % Nn;
    g_tp[t * Nn + n] = (t < NTILES) ? g_colptr[n] + g_off2[n * NCH + 2 * t]
                                    : g_colptr[n + 1];
}

__global__ void k3_fill(const float* __restrict__ S) {
    const int n = blockIdx.x * 256 + threadIdx.x;
    const int mc = blockIdx.y;
    int off = g_colptr[n] + g_off2[n * NCH + mc];
    const int m0 = mc * CHR;
    for (int mm = 0; mm < CHR; mm++) {
        int m = m0 + mm;
        float sv = S[(size_t)m * Nn + n];
        if (fabsf(sv) > ZTOL && off < MAXNNZ) {
            g_rowidx[off] = m; g_colidx[off] = n; g_vals[off] = sv; off++;
        }
    }
}

// ---------------------------------------------------------------------------
// KW: per-(bp,entry) weight streams. Coalesced writes per bp.
// ---------------------------------------------------------------------------
__global__ void k_weights() {
    const int total = g_colptr[Nn];
    const int stride = gridDim.x * blockDim.x;
    for (int i = blockIdx.x * blockDim.x + threadIdx.x; i < total; i += stride) {
        int m = g_rowidx[i], n = g_colidx[i];
        float sval = g_vals[i];
        float mo = __int_as_float((m & 127) * Ff);
        const float4* t1p = &g_T1n[n * BP];
        const float4* t2p = &g_T2n[m * BP];
#pragma unroll
        for (int bp = 0; bp < BP; bp++) {
            float4 t1 = t1p[bp];
            float4 t2 = t2p[bp];
            float t = t1.x + t2.x;
            float wgt = sval * ((t >= 0.f) ? t2.y * t1.y : t2.z * t1.z);
            g_mw[bp * MAXNNZ + i] = make_float2(mo, wgt);
        }
    }
}

// ---------------------------------------------------------------------------
// K4: block = (bp, 128 cols). 8 warps x 16 cols each; lanes = f-pairs.
// 128-row Wx tiles staged in 32KB smem; weights streamed from g_mw.
// ---------------------------------------------------------------------------
__global__ void __launch_bounds__(256) k4_out(float* __restrict__ out) {
    __shared__ __align__(16) float smem[8 * 1088];  // stage 8192 < epi 8704
    const int bp = blockIdx.y;
    const int colbase = blockIdx.x * K4COLS;
    const int w = threadIdx.x >> 5, lane = threadIdx.x & 31;
    const int nw0 = colbase + w * 16;

    float acc0[16], acc1[16];
#pragma unroll
    for (int c = 0; c < 16; c++) { acc0[c] = 0.f; acc1[c] = 0.f; }

    const float4* wxsrc = (const float4*)(g_Wx + (size_t)bp * Nn * Ff);
    const float2* __restrict__ mw = g_mw + (size_t)bp * MAXNNZ;

    for (int t = 0; t < NTILES; t++) {
        const float4* src = wxsrc + t * 128 * (Ff / 4);
        float4* dst4 = (float4*)smem;
#pragma unroll
        for (int q = 0; q < 8; q++)
            dst4[threadIdx.x + q * 256] = src[threadIdx.x + q * 256];
        __syncthreads();

#pragma unroll
        for (int c = 0; c < 16; c++) {
            const int n = nw0 + c;
            int lo = g_tp[t * Nn + n];
            int hi = g_tp[(t + 1) * Nn + n];
            float a0 = acc0[c], a1 = acc1[c];
#pragma unroll 2
            for (int i = lo; i < hi; i++) {
                float2 e = mw[i];
                int mo = __float_as_int(e.x);
                float2 wx = *(const float2*)(smem + mo + 2 * lane);
                a0 = fmaf(e.y, wx.x, a0);
                a1 = fmaf(e.y, wx.y, a1);
            }
            acc0[c] = a0; acc1[c] = a1;
        }
        __syncthreads();
    }

    // Epilogue: per-warp transpose, coalesced 64B-segment stores.
    float* sT = smem + w * 1088;                 // 64 rows x 17
#pragma unroll
    for (int c = 0; c < 16; c++) {
        sT[(2 * lane)     * 17 + c] = fmaxf(acc0[c], 0.f);
        sT[(2 * lane + 1) * 17 + c] = fmaxf(acc1[c], 0.f);
    }
    __syncwarp();
    const int b = bp >> 2, p = bp & 3;
#pragma unroll
    for (int j = 0; j < 32; j++) {
        int f = j * 2 + (lane >> 4);
        int c = lane & 15;
        out[((size_t)b * (Pp * Ff) + p * Ff + f) * Nn + nw0 + c] = sT[f * 17 + c];
    }
}

// ---------------------------------------------------------------------------
extern "C" void kernel_launch(void* const* d_in, const int* in_sizes, int n_in,
                              void* d_out, int out_size) {
    const float* x = (const float*)d_in[0];
    const float* a = (const float*)d_in[1];
    const float* W = (const float*)d_in[2];
    const float* S = (const float*)d_in[3];
    float* out = (float*)d_out;

    k1_wx<<<dim3(8, Pp, Bb), 256>>>(x, a, W);
    k3_count<<<dim3(8, NCH), 256>>>(S);
    k3_offs<<<256, 256>>>();
    k3_scan<<<1, 1024>>>();
    k3_tp<<<136, 256>>>();
    k3_fill<<<dim3(8, NCH), 256>>>(S);
    k2_rowstats<<<Nn, 256>>>(S);
    k_weights<<<1024, 256>>>();
    k4_out<<<dim3(Nn / K4COLS, BP), 256>>>(out);
}